// round 1
// baseline (speedup 1.0000x reference)
#include <cuda_runtime.h>
#include <limits.h>
#include <stdint.h>

// Problem constants
#define BATCH 32
#define NPTS  131072            // 2^17
#define BN    (BATCH*NPTS)      // 4194304
#define TSEL  32768
#define CELL  0.05f

// Hash table: BN max uniques, 2^23 slots -> load factor <= 0.5
#define HBITS 23
#define HSIZE (1<<HBITS)
#define HMASK (HSIZE-1)
#define EMPTYK (-1)

// Scan config: 1024 blocks x 4096 elements (256 thr x 16)
#define NBLK  1024
#define CHUNK 4096
#define SCANT 256
#define ITEMS 16

// Output layout (flattened, concatenated, all f32)
#define OFF_Y    0
#define OFF_IDX  (BATCH*TSEL*3)             // 3145728
#define OFF_MASK (OFF_IDX + BATCH*TSEL*2)   // 5242880
#define OFF_UL   (OFF_MASK + BATCH*TSEL)    // 6291456
#define OFF_ULI  (OFF_UL + BN)              // 10485760

// Scratch (no allocations allowed -> __device__ globals)
__device__ int d_hkey[HSIZE];
__device__ int d_hval[HSIZE];
__device__ int d_slot[BN];
__device__ unsigned char d_flag[BN];
__device__ int d_bsum[NBLK];
__device__ int d_boff[NBLK];
__device__ int d_pbatch[BATCH+1];
__device__ int d_ming, d_maxg;

__device__ __forceinline__ int quant(float v) {
    return (int)rintf(__fdiv_rn(v, CELL));
}

// ---------------------------------------------------------------------------
// K1: init hash table, min/max scalars, SENT-fill ul_idx_inv output region
__global__ void k_init(float* __restrict__ out) {
    unsigned i = blockIdx.x * blockDim.x + threadIdx.x;
    unsigned stride = gridDim.x * blockDim.x;
    for (unsigned j = i; j < (unsigned)HSIZE; j += stride) {
        d_hkey[j] = EMPTYK;
        d_hval[j] = INT_MAX;
        if (j < (unsigned)BN) out[OFF_ULI + j] = (float)BN;  // SENT = BN, exact in f32
    }
    if (i == 0) { d_ming = INT_MAX; d_maxg = INT_MIN; }
}

// ---------------------------------------------------------------------------
// K2: global min/max over quantized grid coords
__global__ void k_minmax(const float* __restrict__ x) {
    int i = blockIdx.x * blockDim.x + threadIdx.x;
    int stride = gridDim.x * blockDim.x;
    int mn = INT_MAX, mx = INT_MIN;
    for (int j = i; j < BN * 3; j += stride) {
        int g = quant(x[j]);
        mn = min(mn, g);
        mx = max(mx, g);
    }
    #pragma unroll
    for (int o = 16; o; o >>= 1) {
        mn = min(mn, __shfl_xor_sync(0xFFFFFFFFu, mn, o));
        mx = max(mx, __shfl_xor_sync(0xFFFFFFFFu, mx, o));
    }
    __shared__ int smn[8], smx[8];
    int lane = threadIdx.x & 31, wid = threadIdx.x >> 5;
    if (lane == 0) { smn[wid] = mn; smx[wid] = mx; }
    __syncthreads();
    if (threadIdx.x == 0) {
        int nwarp = blockDim.x >> 5;
        for (int k = 1; k < nwarp; k++) { mn = min(mn, smn[k]); mx = max(mx, smx[k]); }
        atomicMin(&d_ming, mn);
        atomicMax(&d_maxg, mx);
    }
}

// ---------------------------------------------------------------------------
// K3: compute lin, insert into hash (claim slot via CAS, atomicMin first index)
__global__ void k_insert(const float* __restrict__ x) {
    int i = blockIdx.x * blockDim.x + threadIdx.x;
    if (i >= BN) return;
    int ming = d_ming;
    int gs   = d_maxg - ming + 2;
    int g0 = quant(x[3*i+0]) - ming;
    int g1 = quant(x[3*i+1]) - ming;
    int g2 = quant(x[3*i+2]) - ming;
    int b = i >> 17;
    // int32 arithmetic matching jnp (two's-complement wrap via unsigned mults)
    unsigned ugs = (unsigned)gs;
    unsigned lin_u = ugs*(ugs*(unsigned)g0 + (unsigned)g1) + (unsigned)g2
                   + (ugs*ugs*ugs) * (unsigned)b;
    int lin = (int)lin_u;

    unsigned h = ((unsigned)lin * 2654435761u) >> (32 - HBITS);
    while (true) {
        int k = __ldcg(&d_hkey[h]);          // L2 read (coherent point)
        if (k == lin) break;
        if (k == EMPTYK) {
            int old = atomicCAS(&d_hkey[h], EMPTYK, lin);
            if (old == EMPTYK || old == lin) break;
        }
        h = (h + 1) & HMASK;
    }
    atomicMin(&d_hval[h], i);
    d_slot[i] = (int)h;
}

// ---------------------------------------------------------------------------
// K4: first-occurrence flags + per-block sums (scan pass A)
__global__ void k_flags() {
    int base = blockIdx.x * CHUNK;
    int s = 0;
    #pragma unroll
    for (int r = 0; r < ITEMS; r++) {
        int i  = base + r * SCANT + threadIdx.x;
        int sl = d_slot[i];
        int f  = __ldcg(&d_hval[sl]);
        unsigned char fl = (f == i);
        d_flag[i] = fl;
        s += fl;
    }
    #pragma unroll
    for (int o = 16; o; o >>= 1) s += __shfl_xor_sync(0xFFFFFFFFu, s, o);
    __shared__ int ws[8];
    int lane = threadIdx.x & 31, wid = threadIdx.x >> 5;
    if (lane == 0) ws[wid] = s;
    __syncthreads();
    if (threadIdx.x == 0) {
        int tot = 0;
        #pragma unroll
        for (int k = 0; k < 8; k++) tot += ws[k];
        d_bsum[blockIdx.x] = tot;
    }
}

// ---------------------------------------------------------------------------
// K5: scan the 1024 block sums; emit per-block offsets + per-batch boundaries
__global__ void k_scan2() {
    __shared__ int sh[NBLK];
    int t = threadIdx.x;
    int v = d_bsum[t];
    sh[t] = v;
    __syncthreads();
    for (int o = 1; o < NBLK; o <<= 1) {
        int add = (t >= o) ? sh[t - o] : 0;
        __syncthreads();
        sh[t] += add;
        __syncthreads();
    }
    int incl = sh[t];
    int excl = incl - v;
    d_boff[t] = excl;
    if ((t & 31) == 0) d_pbatch[t >> 5] = excl;   // N/CHUNK = 32 blocks per batch
    if (t == NBLK - 1) d_pbatch[BATCH] = incl;
}

// ---------------------------------------------------------------------------
// K6: final pass — full exclusive prefix per point, scatter ranks into hash,
//     scatter ul_idx_inv, and do the per-batch stable-partition top-T select
__global__ void k_final(const float* __restrict__ x, float* __restrict__ out) {
    __shared__ int pb[BATCH + 1];
    __shared__ int wsum[8];
    __shared__ int wexc[8];
    int t = threadIdx.x;
    if (t <= BATCH) pb[t] = d_pbatch[t];

    int i0 = blockIdx.x * CHUNK + t * ITEMS;
    uint4 v4 = *(const uint4*)(d_flag + i0);
    unsigned w[4] = {v4.x, v4.y, v4.z, v4.w};

    int pre[ITEMS];
    int c = 0;
    #pragma unroll
    for (int e = 0; e < ITEMS; e++) {
        pre[e] = c;
        c += (w[e >> 2] >> ((e & 3) * 8)) & 1;
    }
    int lane = t & 31, wid = t >> 5;
    int inc = c;
    #pragma unroll
    for (int o = 1; o < 32; o <<= 1) {
        int u = __shfl_up_sync(0xFFFFFFFFu, inc, o);
        if (lane >= o) inc += u;
    }
    if (lane == 31) wsum[wid] = inc;
    __syncthreads();
    if (t < 8) {
        int val = wsum[t];
        int ic = val;
        #pragma unroll
        for (int o = 1; o < 8; o <<= 1) {
            int u = __shfl_up_sync(0xFFu, ic, o);
            if (t >= o) ic += u;
        }
        wexc[t] = ic - val;
    }
    __syncthreads();
    int thOff = d_boff[blockIdx.x] + wexc[wid] + (inc - c);

    #pragma unroll
    for (int e = 0; e < ITEMS; e++) {
        int i   = i0 + e;
        int isf = (w[e >> 2] >> ((e & 3) * 8)) & 1;
        int p   = thOff + pre[e];           // global exclusive prefix of flags
        int b   = i >> 17;
        int il  = i & (NPTS - 1);
        int r   = p - pb[b];                // firsts strictly before i, this batch
        int Kb  = pb[b + 1] - pb[b];        // total firsts this batch
        int sel;
        if (isf) {
            d_hkey[d_slot[i]] = p;          // reuse key slot as appearance rank
            out[OFF_ULI + p] = (float)i;    // ul_idx_inv (p is monotone in i)
            sel = (r < TSEL) ? r : -1;
        } else {
            int tt = Kb + (il - r);         // after all firsts, non-firsts by index
            sel = (tt < TSEL) ? tt : -1;
        }
        if (sel >= 0) {
            float y0 = CELL * rintf(__fdiv_rn(x[3*i+0], CELL));
            float y1 = CELL * rintf(__fdiv_rn(x[3*i+1], CELL));
            float y2 = CELL * rintf(__fdiv_rn(x[3*i+2], CELL));
            int o = b * TSEL + sel;
            out[OFF_Y + 3*o + 0] = y0;
            out[OFF_Y + 3*o + 1] = y1;
            out[OFF_Y + 3*o + 2] = y2;
            out[OFF_IDX + 2*o + 0] = (float)b;
            out[OFF_IDX + 2*o + 1] = (float)il;
            out[OFF_MASK + o] = isf ? 1.0f : 0.0f;
        }
    }
}

// ---------------------------------------------------------------------------
// K7: ul_idx[i] = appearance rank of i's voxel (gather rank from hash slot)
__global__ void k_ulidx(float* __restrict__ out) {
    int i = blockIdx.x * blockDim.x + threadIdx.x;
    if (i >= BN) return;
    int rank = d_hkey[d_slot[i]];
    out[OFF_UL + i] = (float)rank;
}

// ---------------------------------------------------------------------------
extern "C" void kernel_launch(void* const* d_in, const int* in_sizes, int n_in,
                              void* d_out, int out_size) {
    const float* x = (const float*)d_in[0];
    float* out = (float*)d_out;
    (void)in_sizes; (void)n_in; (void)out_size;

    k_init  <<<4096, 1024>>>(out);
    k_minmax<<<2048, 256>>>(x);
    k_insert<<<BN / 256, 256>>>(x);
    k_flags <<<NBLK, SCANT>>>();
    k_scan2 <<<1, NBLK>>>();
    k_final <<<NBLK, SCANT>>>(x, out);
    k_ulidx <<<BN / 256, 256>>>(out);
}